// round 2
// baseline (speedup 1.0000x reference)
#include <cuda_runtime.h>
#include <math.h>

#define NPROP 1000
#define NCLS  91
#define TOPK  100
#define NPAD  1024
#define SCORE_TH 0.05f
#define NMS_TH   0.5f
#define MIN_SIZE 1.0f
#define BBOX_CLIP 4.1351665567423f   /* log(1000/16) */

__device__ __forceinline__ float read_dim(const void* p) {
    // image_h / image_w may arrive as int32, int64 (low word), or float32.
    int iv = *(const int*)p;
    if (iv >= 1 && iv <= 100000) return (float)iv;        // int32 / int64 low word
    float fv = __int_as_float(iv);
    if (fv >= 1.0f && fv <= 100000.0f) return fv;          // float32
    return (float)iv;                                       // fallback
}

__global__ __launch_bounds__(NPAD, 1)
void roi_heads_kernel(const float* __restrict__ class_logit,   // [N, C]
                      const float* __restrict__ box_reg,       // [N, C*4]
                      const float* __restrict__ proposal,      // [N, 4]
                      const void*  __restrict__ p_img_h,
                      const void*  __restrict__ p_img_w,
                      float* __restrict__ out, int out_size)
{
    const int c   = blockIdx.x + 1;     // foreground class 1..90
    const int tid = threadIdx.x;

    __shared__ float s_box[NPROP * 4];   // decoded+clipped boxes (pre-sort order)
    __shared__ float s_key[NPAD];        // masked score (sort key)
    __shared__ int   s_idx[NPAD];        // payload: original index
    __shared__ float s_sbox[NPROP * 4];  // boxes in sorted order
    __shared__ unsigned char s_keep[NPAD];
    __shared__ int   s_list[TOPK];
    __shared__ int   s_cnt;

    const float img_h = read_dim(p_img_h);
    const float img_w = read_dim(p_img_w);

    // ---- per-proposal: softmax score for class c, decode, clip, validity ----
    if (tid < NPROP) {
        const float* row = class_logit + tid * NCLS;
        float m = row[0];
        #pragma unroll 13
        for (int j = 1; j < NCLS; ++j) m = fmaxf(m, row[j]);
        float ssum = 0.0f;
        #pragma unroll 13
        for (int j = 0; j < NCLS; ++j) ssum += expf(row[j] - m);
        const float score = expf(row[c] - m) / ssum;

        const float x1 = proposal[tid * 4 + 0];
        const float y1 = proposal[tid * 4 + 1];
        const float x2 = proposal[tid * 4 + 2];
        const float y2 = proposal[tid * 4 + 3];
        const float w  = x2 - x1;
        const float h  = y2 - y1;
        const float cx = x1 + 0.5f * w;
        const float cy = y1 + 0.5f * h;

        const float* d = box_reg + tid * (NCLS * 4) + c * 4;
        const float dx = d[0] * 0.1f;
        const float dy = d[1] * 0.1f;
        const float dw = fminf(d[2] * 0.2f, BBOX_CLIP);
        const float dh = fminf(d[3] * 0.2f, BBOX_CLIP);

        const float pcx = dx * w + cx;
        const float pcy = dy * h + cy;
        const float pw  = expf(dw) * w;
        const float ph  = expf(dh) * h;

        float bx1 = pcx - 0.5f * pw;
        float by1 = pcy - 0.5f * ph;
        float bx2 = pcx + 0.5f * pw;
        float by2 = pcy + 0.5f * ph;

        bx1 = fminf(fmaxf(bx1, 0.0f), img_w);
        by1 = fminf(fmaxf(by1, 0.0f), img_h);
        bx2 = fminf(fmaxf(bx2, 0.0f), img_w);
        by2 = fminf(fmaxf(by2, 0.0f), img_h);

        const float bw = bx2 - bx1;
        const float bh = by2 - by1;
        const bool valid = (score >= SCORE_TH) && (bw >= MIN_SIZE) && (bh >= MIN_SIZE);

        s_box[tid * 4 + 0] = bx1;
        s_box[tid * 4 + 1] = by1;
        s_box[tid * 4 + 2] = bx2;
        s_box[tid * 4 + 3] = by2;
        s_key[tid] = valid ? score : -1.0f;
        s_idx[tid] = tid;
    } else {
        s_key[tid] = -2.0f;   // padding sinks below all real entries (incl. -1)
        s_idx[tid] = tid;
    }
    __syncthreads();

    // ---- bitonic sort, 1024 elems: descending score, ties -> ascending idx ----
    for (int k = 2; k <= NPAD; k <<= 1) {
        for (int j = k >> 1; j > 0; j >>= 1) {
            const int ixj = tid ^ j;
            if (ixj > tid) {
                const float k0 = s_key[tid], k1 = s_key[ixj];
                const int   i0 = s_idx[tid], i1 = s_idx[ixj];
                // "after" in final (descending) order
                const bool after = (k0 < k1) || (k0 == k1 && i0 > i1);
                const bool doswap = ((tid & k) == 0) ? after : !after;
                if (doswap) {
                    s_key[tid] = k1; s_key[ixj] = k0;
                    s_idx[tid] = i1; s_idx[ixj] = i0;
                }
            }
            __syncthreads();
        }
    }

    // ---- gather boxes into sorted order; init keep = valid ----
    if (tid < NPROP) {
        const int src = s_idx[tid];     // always < NPROP (padding keys sank)
        s_sbox[tid * 4 + 0] = s_box[src * 4 + 0];
        s_sbox[tid * 4 + 1] = s_box[src * 4 + 1];
        s_sbox[tid * 4 + 2] = s_box[src * 4 + 2];
        s_sbox[tid * 4 + 3] = s_box[src * 4 + 3];
    }
    s_keep[tid] = (s_key[tid] >= 0.0f) ? 1 : 0;
    __syncthreads();

    // ---- greedy NMS. keep flags are monotone (1 -> 0), so iterations where
    // keep[i]==0 can be skipped without a barrier; barrier only after a
    // suppression round actually writes. ----
    for (int i = 0; i < NPROP - 1; ++i) {
        if (!s_keep[i]) continue;       // uniform read, finalized value
        const float ax1 = s_sbox[i * 4 + 0];
        const float ay1 = s_sbox[i * 4 + 1];
        const float ax2 = s_sbox[i * 4 + 2];
        const float ay2 = s_sbox[i * 4 + 3];
        const float area_a = (ax2 - ax1) * (ay2 - ay1);

        const int j = tid;
        if (j > i && j < NPROP && s_keep[j]) {
            const float bx1 = s_sbox[j * 4 + 0];
            const float by1 = s_sbox[j * 4 + 1];
            const float bx2 = s_sbox[j * 4 + 2];
            const float by2 = s_sbox[j * 4 + 3];
            const float area_b = (bx2 - bx1) * (by2 - by1);
            const float lx = fmaxf(ax1, bx1);
            const float ly = fmaxf(ay1, by1);
            const float rx = fminf(ax2, bx2);
            const float ry = fminf(ay2, by2);
            const float iw = fmaxf(rx - lx, 0.0f);
            const float ih = fmaxf(ry - ly, 0.0f);
            const float inter = iw * ih;
            const float uni   = fmaxf(area_a + area_b - inter, 1e-6f);
            if (inter / uni > NMS_TH) s_keep[j] = 0;
        }
        __syncthreads();
    }

    // ---- compact first TOPK kept (they are already in descending order) ----
    if (tid == 0) {
        int cnt = 0;
        for (int i = 0; i < NPROP && cnt < TOPK; ++i)
            if (s_keep[i]) s_list[cnt++] = i;
        s_cnt = cnt;
    }
    __syncthreads();

    // ---- write output: dets [9000,5] then labels [9000] (as float) ----
    if (tid < TOPK) {
        const int r = (c - 1) * TOPK + tid;
        float b0 = 0.f, b1 = 0.f, b2 = 0.f, b3 = 0.f, sc = 0.f, lab = 0.f;
        if (tid < s_cnt) {
            const int j = s_list[tid];
            b0 = s_sbox[j * 4 + 0];
            b1 = s_sbox[j * 4 + 1];
            b2 = s_sbox[j * 4 + 2];
            b3 = s_sbox[j * 4 + 3];
            sc = s_key[j];
            lab = (float)c;
        }
        out[r * 5 + 0] = b0;
        out[r * 5 + 1] = b1;
        out[r * 5 + 2] = b2;
        out[r * 5 + 3] = b3;
        out[r * 5 + 4] = sc;
        const int dets_elems = (NCLS - 1) * TOPK * 5;        // 45000
        if (out_size >= dets_elems + (NCLS - 1) * TOPK)
            out[dets_elems + r] = lab;
    }
}

extern "C" void kernel_launch(void* const* d_in, const int* in_sizes, int n_in,
                              void* d_out, int out_size)
{
    const float* class_logit = (const float*)d_in[0];
    const float* box_reg     = (const float*)d_in[1];
    const float* proposal    = (const float*)d_in[2];
    const void*  img_h       = d_in[3];
    const void*  img_w       = d_in[4];
    (void)in_sizes; (void)n_in;

    roi_heads_kernel<<<NCLS - 1, NPAD>>>(class_logit, box_reg, proposal,
                                         img_h, img_w,
                                         (float*)d_out, out_size);
}